// round 1
// baseline (speedup 1.0000x reference)
#include <cuda_runtime.h>
#include <stdint.h>

// Problem constants
static constexpr int kN = 50000;
static constexpr int kE = 600000;
static constexpr int kM = 128;
static constexpr int kNCRYS = 256;

// Output layout (floats): ek [E,128] | vi [N,128] | global_fea [256,256] | atom_nbr_fea [N,256]
static constexpr size_t OFF_VI   = (size_t)kE * kM;                 // 76,800,000
static constexpr size_t OFF_GLOB = OFF_VI + (size_t)kN * kM;        // 83,200,000
static constexpr size_t OFF_ANF  = OFF_GLOB + (size_t)kNCRYS * 256; // 83,265,536

// ---------------- scratch (device globals; no allocations allowed) ----------
__device__ float g_rho[(size_t)kN * kM];    // segment_sum(ek_raw/nn)
__device__ float g_eksum[(size_t)kN * kM];  // segment_sum((nbr+ek_raw)/nn)
__device__ float g_viraw[(size_t)kN * kM];  // node MLP output pre-BN
__device__ float g_bnsum[kM];
__device__ float g_bnsumsq[kM];
__device__ float g_bnscale[kM];
__device__ float g_bnshift[kM];

// ---------------- helpers ---------------------------------------------------
__device__ __forceinline__ uint32_t f2tf(float f) {
  uint32_t u;
  asm("cvt.rna.tf32.f32 %0, %1;" : "=r"(u) : "f"(f));
  return u;
}
__device__ __forceinline__ float lrelu(float v) { return v >= 0.f ? v : 0.2f * v; }

__device__ __forceinline__ void mma_tf32(float* c, const uint32_t* a, uint32_t b0, uint32_t b1) {
  asm volatile(
      "mma.sync.aligned.m16n8k8.row.col.f32.tf32.tf32.f32 "
      "{%0,%1,%2,%3}, {%4,%5,%6,%7}, {%8,%9}, {%0,%1,%2,%3};\n"
      : "+f"(c[0]), "+f"(c[1]), "+f"(c[2]), "+f"(c[3])
      : "r"(a[0]), "r"(a[1]), "r"(a[2]), "r"(a[3]), "r"(b0), "r"(b1));
}
__device__ __forceinline__ void red2(float* p, float x, float y) {
  asm volatile("red.global.add.v2.f32 [%0], {%1,%2};" :: "l"(p), "f"(x), "f"(y) : "memory");
}
__device__ __forceinline__ void red4(float* p, float4 v) {
  asm volatile("red.global.add.v4.f32 [%0], {%1,%2,%3,%4};"
               :: "l"(p), "f"(v.x), "f"(v.y), "f"(v.z), "f"(v.w) : "memory");
}

// Smem geometry:
//   As: 128 x 132 u32 (tf32 A operand, padded for conflict-free frag loads)  67584 B
//   Ws: frag-major weight chunk: 16 ksteps x 16 ntiles x 32 lanes x 2        65536 B
//   Nbr (edge kernel only): 128 x 132 fp32                                   67584 B
static constexpr int AS_STRIDE = 132;
static constexpr int AS_BYTES = 128 * AS_STRIDE * 4;   // 67584
static constexpr int WS_BYTES = 16384 * 4;             // 65536

// Stage one 128-K-row chunk of W[128][128] (row-major in->out) into frag-major tf32.
__device__ __forceinline__ void stage_W(const float* __restrict__ Wg, uint32_t* __restrict__ Ws) {
  for (int i = threadIdx.x; i < 128 * 128; i += 256) {
    int k = i >> 7, n = i & 127;
    uint32_t v = f2tf(Wg[i]);
    int lane = ((n & 7) << 2) | (k & 3);
    int idx = ((((k >> 3) << 4) + (n >> 3)) << 6) + (lane << 1) + ((k >> 2) & 1);
    Ws[idx] = v;
  }
}

// Stage gathered rows (atom_in_fea[sidx[row]]) as tf32 into As.
__device__ __forceinline__ void stage_A_idx(const float* __restrict__ base,
                                            const int* __restrict__ sidx,
                                            uint32_t* __restrict__ As, int rows_valid) {
  for (int i = threadIdx.x; i < 128 * 32; i += 256) {
    int row = i >> 5, c4 = (i & 31) << 2;
    float4 v = make_float4(0.f, 0.f, 0.f, 0.f);
    if (row < rows_valid)
      v = *reinterpret_cast<const float4*>(base + (size_t)sidx[row] * kM + c4);
    *reinterpret_cast<uint4*>(As + row * AS_STRIDE + c4) =
        make_uint4(f2tf(v.x), f2tf(v.y), f2tf(v.z), f2tf(v.w));
  }
}

// Stage contiguous rows [r0, r0+128) as tf32 into As.
__device__ __forceinline__ void stage_A_direct(const float* __restrict__ base, int r0,
                                               uint32_t* __restrict__ As, int rows_valid) {
  for (int i = threadIdx.x; i < 128 * 32; i += 256) {
    int row = i >> 5, c4 = (i & 31) << 2;
    float4 v = make_float4(0.f, 0.f, 0.f, 0.f);
    if (row < rows_valid)
      v = *reinterpret_cast<const float4*>(base + (size_t)(r0 + row) * kM + c4);
    *reinterpret_cast<uint4*>(As + row * AS_STRIDE + c4) =
        make_uint4(f2tf(v.x), f2tf(v.y), f2tf(v.z), f2tf(v.w));
  }
}

// Stage nbr_fea rows: tf32 into As AND fp32 into Nbr (for the residual epilogue).
__device__ __forceinline__ void stage_nbr(const float* __restrict__ nbr_fea, int e0,
                                          uint32_t* __restrict__ As, float* __restrict__ Nbr,
                                          int rows_valid) {
  for (int i = threadIdx.x; i < 128 * 32; i += 256) {
    int row = i >> 5, c4 = (i & 31) << 2;
    float4 v = make_float4(0.f, 0.f, 0.f, 0.f);
    if (row < rows_valid)
      v = *reinterpret_cast<const float4*>(nbr_fea + (size_t)(e0 + row) * kM + c4);
    *reinterpret_cast<float4*>(Nbr + row * AS_STRIDE + c4) = v;
    *reinterpret_cast<uint4*>(As + row * AS_STRIDE + c4) =
        make_uint4(f2tf(v.x), f2tf(v.y), f2tf(v.z), f2tf(v.w));
  }
}

__device__ __forceinline__ void zero_acc(float acc[4][4][4]) {
#pragma unroll
  for (int a = 0; a < 4; a++)
#pragma unroll
    for (int b = 0; b < 4; b++)
#pragma unroll
      for (int c = 0; c < 4; c++) acc[a][b][c] = 0.f;
}

// One 128x128x128 GEMM chunk: acc += As(128x128 tf32) @ Wchunk(128x128 tf32).
// Warp grid 2(m) x 4(n); each warp owns 64x32 (4 mtiles x 4 ntiles of m16n8k8).
__device__ __forceinline__ void gemm_chunk(const uint32_t* __restrict__ As,
                                           const uint32_t* __restrict__ Ws,
                                           float acc[4][4][4]) {
  const int lane = threadIdx.x & 31, warp = threadIdx.x >> 5;
  const int wm = warp >> 2, wn = warp & 3;
  const int g = lane >> 2, t = lane & 3;
#pragma unroll 4
  for (int ks = 0; ks < 16; ks++) {
    uint32_t a[4][4];
#pragma unroll
    for (int mt = 0; mt < 4; mt++) {
      const uint32_t* ap = As + (wm * 64 + mt * 16 + g) * AS_STRIDE + ks * 8 + t;
      a[mt][0] = ap[0];
      a[mt][1] = ap[8 * AS_STRIDE];
      a[mt][2] = ap[4];
      a[mt][3] = ap[8 * AS_STRIDE + 4];
    }
    const uint32_t* wb = Ws + (ks * 16 + wn * 4) * 64 + lane * 2;
#pragma unroll
    for (int nt = 0; nt < 4; nt++) {
      uint2 b = *reinterpret_cast<const uint2*>(wb + nt * 64);
#pragma unroll
      for (int mt = 0; mt < 4; mt++) mma_tf32(acc[mt][nt], a[mt], b.x, b.y);
    }
  }
}

// acc + bias -> lrelu -> As (tf32), ready as next layer's A operand.
__device__ __forceinline__ void write_H(float acc[4][4][4], const float* __restrict__ bias,
                                        uint32_t* __restrict__ As) {
  const int lane = threadIdx.x & 31, warp = threadIdx.x >> 5;
  const int wm = warp >> 2, wn = warp & 3;
  const int g = lane >> 2, t = lane & 3;
#pragma unroll
  for (int nt = 0; nt < 4; nt++) {
    int col0 = wn * 32 + nt * 8 + 2 * t;
    float b0 = __ldg(bias + col0), b1 = __ldg(bias + col0 + 1);
#pragma unroll
    for (int mt = 0; mt < 4; mt++) {
      int r0 = wm * 64 + mt * 16 + g;
      uint2 u;
      u.x = f2tf(lrelu(acc[mt][nt][0] + b0));
      u.y = f2tf(lrelu(acc[mt][nt][1] + b1));
      *reinterpret_cast<uint2*>(As + r0 * AS_STRIDE + col0) = u;
      u.x = f2tf(lrelu(acc[mt][nt][2] + b0));
      u.y = f2tf(lrelu(acc[mt][nt][3] + b1));
      *reinterpret_cast<uint2*>(As + (r0 + 8) * AS_STRIDE + col0) = u;
    }
  }
}

// ---------------- kernel 1: init --------------------------------------------
__global__ void init_kernel(float* __restrict__ out_glob) {
  size_t i = (size_t)blockIdx.x * blockDim.x + threadIdx.x;
  size_t total = (size_t)kN * kM;
  if (i < total) { g_rho[i] = 0.f; g_eksum[i] = 0.f; }
  if (i < (size_t)kNCRYS * 256) out_glob[i] = 0.f;
  if (i < kM) { g_bnsum[i] = 0.f; g_bnsumsq[i] = 0.f; }
}

// ---------------- kernel 2: fused edge MLP ----------------------------------
__global__ __launch_bounds__(256, 1) void edge_mlp_kernel(
    const float* __restrict__ atom, const float* __restrict__ nbr_fea,
    const float* __restrict__ num_nbrs, const int* __restrict__ idx1,
    const int* __restrict__ idx2,
    const float* __restrict__ We1, const float* __restrict__ be1,
    const float* __restrict__ We2, const float* __restrict__ be2,
    const float* __restrict__ We3, const float* __restrict__ be3,
    float* __restrict__ out_ek) {
  extern __shared__ unsigned char sm_raw[];
  uint32_t* As = reinterpret_cast<uint32_t*>(sm_raw);
  uint32_t* Ws = reinterpret_cast<uint32_t*>(sm_raw + AS_BYTES);
  float* Nbr = reinterpret_cast<float*>(sm_raw + AS_BYTES + WS_BYTES);
  int* sidx1 = reinterpret_cast<int*>(sm_raw + AS_BYTES + WS_BYTES + AS_BYTES);
  int* sidx2 = sidx1 + 128;
  float* sinv = reinterpret_cast<float*>(sidx2 + 128);

  const int e0 = blockIdx.x * 128;
  const int rows_valid = min(128, kE - e0);

  if (threadIdx.x < 128) {
    int e = e0 + threadIdx.x;
    int i1 = 0, i2 = 0;
    float inv = 0.f;
    if (e < kE) { i1 = idx1[e]; i2 = idx2[e]; inv = 1.f / num_nbrs[i1]; }
    sidx1[threadIdx.x] = i1; sidx2[threadIdx.x] = i2; sinv[threadIdx.x] = inv;
  }
  __syncthreads();

  float acc[4][4][4];
  zero_acc(acc);

  // Layer 1: K = 384 in three 128-chunks [a1 | a2 | nbr]
  stage_A_idx(atom, sidx1, As, rows_valid);
  stage_W(We1, Ws);
  __syncthreads();
  gemm_chunk(As, Ws, acc);
  __syncthreads();

  stage_A_idx(atom, sidx2, As, rows_valid);
  stage_W(We1 + 128 * 128, Ws);
  __syncthreads();
  gemm_chunk(As, Ws, acc);
  __syncthreads();

  stage_nbr(nbr_fea, e0, As, Nbr, rows_valid);
  stage_W(We1 + 256 * 128, Ws);
  __syncthreads();
  gemm_chunk(As, Ws, acc);
  __syncthreads();

  // H1 -> layer 2
  write_H(acc, be1, As);
  stage_W(We2, Ws);
  __syncthreads();
  zero_acc(acc);
  gemm_chunk(As, Ws, acc);
  __syncthreads();

  // H2 -> layer 3
  write_H(acc, be2, As);
  stage_W(We3, Ws);
  __syncthreads();
  zero_acc(acc);
  gemm_chunk(As, Ws, acc);

  // Epilogue: ek_out = nbr + ek_raw; atomically accumulate rho and eksum.
  const int lane = threadIdx.x & 31, warp = threadIdx.x >> 5;
  const int wm = warp >> 2, wn = warp & 3;
  const int g = lane >> 2, t = lane & 3;
#pragma unroll
  for (int nt = 0; nt < 4; nt++) {
    int col0 = wn * 32 + nt * 8 + 2 * t;
    float b0 = __ldg(be3 + col0), b1 = __ldg(be3 + col0 + 1);
#pragma unroll
    for (int mt = 0; mt < 4; mt++) {
#pragma unroll
      for (int h = 0; h < 2; h++) {
        int r = wm * 64 + mt * 16 + g + h * 8;
        int e = e0 + r;
        if (e < kE) {
          float ek0 = acc[mt][nt][2 * h] + b0;
          float ek1 = acc[mt][nt][2 * h + 1] + b1;
          float o0 = ek0 + Nbr[r * AS_STRIDE + col0];
          float o1 = ek1 + Nbr[r * AS_STRIDE + col0 + 1];
          *reinterpret_cast<float2*>(out_ek + (size_t)e * kM + col0) = make_float2(o0, o1);
          float inv = sinv[r];
          size_t off = (size_t)sidx1[r] * kM + col0;
          red2(g_rho + off, ek0 * inv, ek1 * inv);
          red2(g_eksum + off, o0 * inv, o1 * inv);
        }
      }
    }
  }
}

// ---------------- kernel 3: fused node MLP ----------------------------------
__global__ __launch_bounds__(256, 1) void node_mlp_kernel(
    const float* __restrict__ atom,
    const float* __restrict__ Wv1, const float* __restrict__ bv1,
    const float* __restrict__ Wv2, const float* __restrict__ bv2,
    const float* __restrict__ Wv3, const float* __restrict__ bv3) {
  extern __shared__ unsigned char sm_raw[];
  uint32_t* As = reinterpret_cast<uint32_t*>(sm_raw);
  uint32_t* Ws = reinterpret_cast<uint32_t*>(sm_raw + AS_BYTES);

  const int n0 = blockIdx.x * 128;
  const int rows_valid = min(128, kN - n0);

  float acc[4][4][4];
  zero_acc(acc);

  // Layer 1: K = 256 in two chunks [atom | rho]
  stage_A_direct(atom, n0, As, rows_valid);
  stage_W(Wv1, Ws);
  __syncthreads();
  gemm_chunk(As, Ws, acc);
  __syncthreads();

  stage_A_direct(g_rho, n0, As, rows_valid);
  stage_W(Wv1 + 128 * 128, Ws);
  __syncthreads();
  gemm_chunk(As, Ws, acc);
  __syncthreads();

  write_H(acc, bv1, As);
  stage_W(Wv2, Ws);
  __syncthreads();
  zero_acc(acc);
  gemm_chunk(As, Ws, acc);
  __syncthreads();

  write_H(acc, bv2, As);
  stage_W(Wv3, Ws);
  __syncthreads();
  zero_acc(acc);
  gemm_chunk(As, Ws, acc);
  __syncthreads();  // before reusing As as fp32 scratch

  // Epilogue: vi_raw -> gmem scratch + block-level BN partial sums.
  float* Vs = reinterpret_cast<float*>(As);
  const int lane = threadIdx.x & 31, warp = threadIdx.x >> 5;
  const int wm = warp >> 2, wn = warp & 3;
  const int g = lane >> 2, t = lane & 3;
#pragma unroll
  for (int nt = 0; nt < 4; nt++) {
    int col0 = wn * 32 + nt * 8 + 2 * t;
    float b0 = __ldg(bv3 + col0), b1 = __ldg(bv3 + col0 + 1);
#pragma unroll
    for (int mt = 0; mt < 4; mt++) {
#pragma unroll
      for (int h = 0; h < 2; h++) {
        int r = wm * 64 + mt * 16 + g + h * 8;
        float v0 = acc[mt][nt][2 * h] + b0;
        float v1 = acc[mt][nt][2 * h + 1] + b1;
        Vs[r * AS_STRIDE + col0] = v0;
        Vs[r * AS_STRIDE + col0 + 1] = v1;
        if (n0 + r < kN)
          *reinterpret_cast<float2*>(g_viraw + (size_t)(n0 + r) * kM + col0) =
              make_float2(v0, v1);
      }
    }
  }
  __syncthreads();
  if (threadIdx.x < 128) {
    int col = threadIdx.x;
    float s = 0.f, s2 = 0.f;
    for (int r = 0; r < rows_valid; r++) {
      float v = Vs[r * AS_STRIDE + col];
      s += v;
      s2 += v * v;
    }
    atomicAdd(&g_bnsum[col], s);
    atomicAdd(&g_bnsumsq[col], s2);
  }
}

// ---------------- kernel 4: BN finalize -------------------------------------
__global__ void bn_finalize_kernel(const float* __restrict__ gamma,
                                   const float* __restrict__ beta) {
  int t = threadIdx.x;
  if (t < kM) {
    float mu = g_bnsum[t] * (1.f / (float)kN);
    float var = g_bnsumsq[t] * (1.f / (float)kN) - mu * mu;
    float sc = gamma[t] * rsqrtf(var + 1e-5f);
    g_bnscale[t] = sc;
    g_bnshift[t] = beta[t] - mu * sc;
  }
}

// ---------------- kernel 5: apply BN/residual, concat, crystal pooling ------
__global__ void apply_kernel(const float* __restrict__ atom, const int* __restrict__ crys,
                             float* __restrict__ out_vi, float* __restrict__ out_glob,
                             float* __restrict__ out_anf) {
  int i = blockIdx.x * blockDim.x + threadIdx.x;
  if (i >= kN * 32) return;
  int n = i >> 5, q = i & 31;
  int j0 = q << 2;
  float4 a = *reinterpret_cast<const float4*>(atom + (size_t)n * kM + j0);
  float4 vr = *reinterpret_cast<const float4*>(g_viraw + (size_t)n * kM + j0);
  float4 sc = *reinterpret_cast<const float4*>(g_bnscale + j0);
  float4 sh = *reinterpret_cast<const float4*>(g_bnshift + j0);
  float4 v;
  v.x = a.x + vr.x * sc.x + sh.x;
  v.y = a.y + vr.y * sc.y + sh.y;
  v.z = a.z + vr.z * sc.z + sh.z;
  v.w = a.w + vr.w * sc.w + sh.w;
  float4 ekv = *reinterpret_cast<const float4*>(g_eksum + (size_t)n * kM + j0);

  *reinterpret_cast<float4*>(out_vi + (size_t)n * kM + j0) = v;
  *reinterpret_cast<float4*>(out_anf + (size_t)n * 256 + j0) = v;
  *reinterpret_cast<float4*>(out_anf + (size_t)n * 256 + 128 + j0) = ekv;

  int cr = crys[n];
  red4(out_glob + (size_t)cr * 256 + j0, v);
  red4(out_glob + (size_t)cr * 256 + 128 + j0, ekv);
}

// ---------------- launcher ---------------------------------------------------
extern "C" void kernel_launch(void* const* d_in, const int* in_sizes, int n_in,
                              void* d_out, int out_size) {
  const float* atom     = (const float*)d_in[0];
  const float* nbr_fea  = (const float*)d_in[1];
  const float* num_nbrs = (const float*)d_in[2];
  const int*   idx1     = (const int*)d_in[3];
  const int*   idx2     = (const int*)d_in[4];
  const int*   crys     = (const int*)d_in[5];
  const float* We1 = (const float*)d_in[6];
  const float* be1 = (const float*)d_in[7];
  const float* We2 = (const float*)d_in[8];
  const float* be2 = (const float*)d_in[9];
  const float* We3 = (const float*)d_in[10];
  const float* be3 = (const float*)d_in[11];
  const float* Wv1 = (const float*)d_in[12];
  const float* bv1 = (const float*)d_in[13];
  const float* Wv2 = (const float*)d_in[14];
  const float* bv2 = (const float*)d_in[15];
  const float* Wv3 = (const float*)d_in[16];
  const float* bv3 = (const float*)d_in[17];
  const float* bn_gamma = (const float*)d_in[18];
  const float* bn_beta  = (const float*)d_in[19];

  float* out = (float*)d_out;
  float* out_ek   = out;
  float* out_vi   = out + OFF_VI;
  float* out_glob = out + OFF_GLOB;
  float* out_anf  = out + OFF_ANF;

  static const int EDGE_SMEM = AS_BYTES + WS_BYTES + AS_BYTES + 1536;  // 202240
  static const int NODE_SMEM = AS_BYTES + WS_BYTES;                    // 133120
  cudaFuncSetAttribute(edge_mlp_kernel, cudaFuncAttributeMaxDynamicSharedMemorySize, EDGE_SMEM);
  cudaFuncSetAttribute(node_mlp_kernel, cudaFuncAttributeMaxDynamicSharedMemorySize, NODE_SMEM);

  init_kernel<<<(kN * kM + 255) / 256, 256>>>(out_glob);

  edge_mlp_kernel<<<(kE + 127) / 128, 256, EDGE_SMEM>>>(
      atom, nbr_fea, num_nbrs, idx1, idx2,
      We1, be1, We2, be2, We3, be3, out_ek);

  node_mlp_kernel<<<(kN + 127) / 128, 256, NODE_SMEM>>>(
      atom, Wv1, bv1, Wv2, bv2, Wv3, bv3);

  bn_finalize_kernel<<<1, 128>>>(bn_gamma, bn_beta);

  apply_kernel<<<(kN * 32 + 255) / 256, 256>>>(atom, crys, out_vi, out_glob, out_anf);
}